// round 15
// baseline (speedup 1.0000x reference)
#include <cuda_runtime.h>
#include <math.h>

#define THREADS 256
#define GRID 592          // 4 * 148 SMs -> exactly one resident wave at occupancy 4
#define BX 144
#define BY 80
#define NBIN (BX * BY)    // 11520 cells, ~40x40.5 px each over the 3W x 3H window
#define CAP 1024          // per-cell capacity (expected peak ~470)
#define MAXPTS 1048576
#define NCORN 128

// Zero-initialized scratch; kernel self-restores zeros after each run.
__device__ unsigned int g_cmax[NCORN];   // key = ~fenc(min d2); 0 == "empty"
__device__ unsigned int g_ctr;
__device__ unsigned int g_bar;
__device__ int g_cnt[NBIN];
__device__ int g_farc;                   // out-of-window points
__device__ int g_ovfc;                   // cell-overflow points
__device__ __align__(16) float2 g_bin[(size_t)NBIN * CAP];
__device__ __align__(16) float2 g_far[MAXPTS];
__device__ __align__(16) float2 g_ovf[MAXPTS];

__device__ __forceinline__ float read_dim(const void* p) {
    int iv = *(const int*)p;
    if (iv > 0 && iv < 1000000) return (float)iv;
    return *(const float*)p;
}

__device__ __forceinline__ unsigned fenc(float f) {
    unsigned b = __float_as_uint(f);
    return (b & 0x80000000u) ? ~b : (b | 0x80000000u);
}
__device__ __forceinline__ float fdec(unsigned k) {
    return __uint_as_float((k & 0x80000000u) ? (k ^ 0x80000000u) : ~k);
}

struct Cam {
    float R00, R01, R02, R10, R11, R12, R20, R21, R22;
    float camx, camy, camz, f, kx0, ky0, Hf;
};

__device__ __forceinline__ Cam make_cam(const float* cam, const float* theta,
                                        const float* va, const void* hp, const void* wp,
                                        float& Wf_out) {
    Cam C;
    const float d2rf = 0.017453292519943295f;
    float rx = __fmul_rn(theta[0], d2rf);
    float ry = __fmul_rn(theta[1], d2rf);
    float rz = __fmul_rn(theta[2], d2rf);
    float cxa = cosf(rx), sxa = sinf(rx);
    float cya = cosf(ry), sya = sinf(ry);
    float cza = cosf(rz), sza = sinf(rz);
    float M01 = __fmul_rn(sya, sxa), M02 = __fmul_rn(sya, cxa);
    float M11 = cxa,                 M12 = -sxa;
    C.R20 = -sya; C.R21 = __fmul_rn(cya, sxa); C.R22 = __fmul_rn(cya, cxa);
    C.R00 = __fmul_rn(cza, cya);
    C.R01 = __fsub_rn(__fmul_rn(cza, M01), __fmul_rn(sza, M11));
    C.R02 = __fsub_rn(__fmul_rn(cza, M02), __fmul_rn(sza, M12));
    C.R10 = __fmul_rn(sza, cya);
    C.R11 = __fadd_rn(__fmul_rn(sza, M01), __fmul_rn(cza, M11));
    C.R12 = __fadd_rn(__fmul_rn(sza, M02), __fmul_rn(cza, M12));
    C.Hf = read_dim(hp);
    Wf_out = read_dim(wp);
    float vr = __fmul_rn(__fmul_rn(va[0], 0.5f), d2rf);
    C.f   = __fdiv_rn(-C.Hf, __fmul_rn(2.0f, tanf(vr)));
    C.kx0 = __fsub_rn(__fmul_rn(Wf_out, 0.5f), 0.5f);
    C.ky0 = __fsub_rn(__fmul_rn(C.Hf, 0.5f), 0.5f);
    C.camx = cam[0]; C.camy = cam[1]; C.camz = cam[2];
    return C;
}

__device__ __forceinline__ float2 project(const Cam& C, const float* pp) {
    float tx = __fadd_rn(pp[0], -C.camx);
    float ty = __fadd_rn(pp[1], -C.camy);
    float tz = __fadd_rn(pp[2], -C.camz);
    float x = __fmaf_rn(tz, C.R02, __fmaf_rn(ty, C.R01, __fmul_rn(tx, C.R00)));
    float y = __fmaf_rn(tz, C.R12, __fmaf_rn(ty, C.R11, __fmul_rn(tx, C.R10)));
    float z = __fmaf_rn(tz, C.R22, __fmaf_rn(ty, C.R21, __fmul_rn(tx, C.R20)));
    float xp = __fdiv_rn(x, z);
    float yp = __fdiv_rn(y, z);
    float u  = __fmaf_rn(C.f, xp, C.kx0);
    float v  = __fmaf_rn(C.f, yp, C.ky0);
    float vf = __fadd_rn(C.Hf, -v);
    return make_float2(u, vf);
}

// d2 with the reference rounding chain (identical to all prior passing rounds).
__device__ __forceinline__ float dist2(float ccx, float ccy, float t1, float2 p) {
    float s   = __fadd_rn(__fmul_rn(p.x, p.x), __fmul_rn(p.y, p.y));
    float t1s = __fadd_rn(t1, s);
    float dot = __fmaf_rn(ccy, p.y, __fmul_rn(ccx, p.x));
    return __fmaf_rn(-2.0f, dot, t1s);
}

// Warp-aggregated list push: one atomic per warp instead of per lane.
__device__ __forceinline__ void warp_push(bool pred, float2 q, int* ctr, float2* list) {
    unsigned mask = __ballot_sync(0xFFFFFFFFu, pred);
    if (pred) {
        int lane   = threadIdx.x & 31;
        int leader = __ffs(mask) - 1;
        int rank   = __popc(mask & ((1u << lane) - 1u));
        int base = 0;
        if (lane == leader) base = atomicAdd(ctr, __popc(mask));
        base = __shfl_sync(mask, base, leader);
        int pos = base + rank;
        if (pos < MAXPTS) list[pos] = q;
    }
}

__global__ void __launch_bounds__(THREADS, 4)
k_main(const float* __restrict__ P, const float* __restrict__ dtc,
       const float* __restrict__ cam, const float* __restrict__ theta,
       const float* __restrict__ va, const void* hp, const void* wp,
       int N, float* __restrict__ out) {
    __shared__ float swarp[8];
    __shared__ float sbest;
    __shared__ bool  isLast;
    __shared__ float red[NCORN];

    const int tid = threadIdx.x;
    const int bid = blockIdx.x;

    float Wf;
    const Cam C = make_cam(cam, theta, va, hp, wp, Wf);

    const float gx0 = -Wf, gy0 = -C.Hf;
    const float icw = __fdiv_rn((float)BX, 3.0f * Wf);
    const float ich = __fdiv_rn((float)BY, 3.0f * C.Hf);
    const float cellmin = fminf(__fdiv_rn(3.0f * Wf, (float)BX),
                                __fdiv_rn(3.0f * C.Hf, (float)BY));

    // ---- Phase 1: project + direct-bucket scatter (each point once) ----
    const int ppb = (N + GRID - 1) / GRID;
    const int i0  = bid * ppb;
    const int i1  = min(N, i0 + ppb);
    for (int base_i = i0; base_i < i1; base_i += THREADS) {
        const int i = base_i + tid;
        float2 q = make_float2(0.0f, 0.0f);
        bool valid = (i < i1);
        bool in_win = false;
        int cell = 0;
        if (valid) {
            q = project(C, P + 3 * i);
            float fx = __fmul_rn(__fadd_rn(q.x, -gx0), icw);
            float fy = __fmul_rn(__fadd_rn(q.y, -gy0), ich);
            in_win = (fx >= 0.0f && fx < (float)BX && fy >= 0.0f && fy < (float)BY);
            if (in_win) cell = (int)fy * BX + (int)fx;
        }
        bool ovf = false;
        if (valid && in_win) {
            int pos = atomicAdd(&g_cnt[cell], 1);
            if (pos < CAP) g_bin[(size_t)cell * CAP + pos] = q;
            else ovf = true;
        }
        // Single-address counters: warp-aggregated (kills atomic serialization).
        warp_push(valid && !in_win, q, &g_farc, g_far);
        warp_push(ovf, q, &g_ovfc, g_ovf);
    }

    // ---- Single grid-wide barrier (all 592 blocks co-resident) ----
    __threadfence();
    __syncthreads();
    if (tid == 0) {
        atomicAdd(&g_bar, 1u);
        while (*((volatile unsigned int*)&g_bar) < (unsigned)gridDim.x) __nanosleep(32);
    }
    __syncthreads();
    __threadfence();

    // ---- Phase 2: blocks 0..127 each resolve one corner ----
    if (bid < NCORN) {
        const float ccx = dtc[2 * bid], ccy = dtc[2 * bid + 1];
        const float t1 = __fadd_rn(__fmul_rn(ccx, ccx), __fmul_rn(ccy, ccy));
        int bcu = (int)(__fmul_rn(__fadd_rn(ccx, -gx0), icw));
        int bcv = (int)(__fmul_rn(__fadd_rn(ccy, -gy0), ich));
        bcu = max(0, min(BX - 1, bcu));
        bcv = max(0, min(BY - 1, bcv));

        float lbest = 3.4e38f;

        // Overflow list (normally empty) must always be included for exactness.
        const int novf = min(g_ovfc, MAXPTS);
        for (int idx = tid; idx < novf; idx += THREADS)
            lbest = fminf(lbest, dist2(ccx, ccy, t1, g_ovf[idx]));

        // 3x3 cell block (rings 0..1): prefetch counts, then scan with MLP.
        int cells[9], cnts[9];
#pragma unroll
        for (int dy = -1; dy <= 1; dy++) {
#pragma unroll
            for (int dx = -1; dx <= 1; dx++) {
                int ii = (dy + 1) * 3 + (dx + 1);
                int x = bcu + dx, y = bcv + dy;
                bool ok = (x >= 0 && x < BX && y >= 0 && y < BY);
                cells[ii] = ok ? (y * BX + x) : 0;
                cnts[ii]  = ok ? min(g_cnt[cells[ii]], CAP) : 0;
            }
        }
#pragma unroll
        for (int ii = 0; ii < 9; ii++) {
            const size_t base = (size_t)cells[ii] * CAP;
            const int cnt = cnts[ii];
#pragma unroll 4
            for (int idx = tid; idx < cnt; idx += THREADS)
                lbest = fminf(lbest, dist2(ccx, ccy, t1, g_bin[base + idx]));
        }

        auto block_min = [&](float v) -> float {
            for (int o = 16; o >= 1; o >>= 1)
                v = fminf(v, __shfl_xor_sync(0xFFFFFFFFu, v, o));
            if ((tid & 31) == 0) swarp[tid >> 5] = v;
            __syncthreads();
            if (tid < 8) {
                float w = swarp[tid];
                for (int o = 4; o >= 1; o >>= 1)
                    w = fminf(w, __shfl_xor_sync(0xFFu, w, o));
                if (tid == 0) sbest = w;
            }
            __syncthreads();
            float r = sbest;
            __syncthreads();
            return r;
        };

        float gbest = block_min(lbest);

        // Outer rings (rare): unscanned cells at chebyshev > r are >= r*cellmin away.
        if (!(__fmul_rn(cellmin, cellmin) > gbest + 64.0f)) {
            const int rmax = (BX > BY ? BX : BY);
            for (int r = 2; r <= rmax; r++) {
                const int xlo = bcu - r, xhi = bcu + r;
                const int ylo = bcv - r, yhi = bcv + r;
                for (int y = ylo; y <= yhi; y++) {
                    if (y < 0 || y >= BY) continue;
                    const bool edge = (y == ylo || y == yhi);
                    const int step = edge ? 1 : (xhi - xlo);
                    for (int x = xlo; x <= xhi; x += step) {
                        if (x < 0 || x >= BX) continue;
                        const int cell = y * BX + x;
                        const int cnt = min(g_cnt[cell], CAP);
                        const size_t base = (size_t)cell * CAP;
#pragma unroll 4
                        for (int idx = tid; idx < cnt; idx += THREADS)
                            lbest = fminf(lbest, dist2(ccx, ccy, t1, g_bin[base + idx]));
                    }
                }
                gbest = block_min(lbest);
                float lb = __fmul_rn((float)r, cellmin);
                if (__fmul_rn(lb, lb) > gbest + 64.0f) break;
            }
        }

        // Far-points fallback: only if the window-edge bound could bind.
        float fbx = fminf(__fadd_rn(ccx, Wf), __fsub_rn(2.0f * Wf, ccx));
        float fby = fminf(__fadd_rn(ccy, C.Hf), __fsub_rn(2.0f * C.Hf, ccy));
        float fb  = fminf(fbx, fby);
        bool need_far = !(fb > 0.0f) || (gbest + 64.0f >= __fmul_rn(fb, fb));
        if (need_far) {
            const int nfar = min(g_farc, MAXPTS);
#pragma unroll 4
            for (int idx = tid; idx < nfar; idx += THREADS)
                lbest = fminf(lbest, dist2(ccx, ccy, t1, g_far[idx]));
            gbest = block_min(lbest);
        }

        if (tid == 0) atomicMax(&g_cmax[bid], ~fenc(gbest));
    }

    // ---- Final: last block sums minima + restores ALL scratch to zero ----
    __threadfence();
    __syncthreads();
    if (tid == 0) {
        unsigned old = atomicAdd(&g_ctr, 1u);
        isLast = (old == gridDim.x - 1u);
    }
    __syncthreads();
    if (isLast) {
        if (tid < NCORN) {
            red[tid] = fdec(~g_cmax[tid]);
            g_cmax[tid] = 0u;
        }
        for (int b = tid; b < NBIN; b += THREADS) g_cnt[b] = 0;
        if (tid == 0) { g_ctr = 0u; g_bar = 0u; g_farc = 0; g_ovfc = 0; }
        __syncthreads();
        for (int off = 64; off > 0; off >>= 1) {
            if (tid < off) red[tid] += red[tid + off];
            __syncthreads();
        }
        if (tid == 0) out[0] = red[0];
    }
}

extern "C" void kernel_launch(void* const* d_in, const int* in_sizes, int n_in,
                              void* d_out, int out_size) {
    const float* PntCld = (const float*)d_in[0];
    const float* dtcCor = (const float*)d_in[1];
    const float* cam    = (const float*)d_in[2];
    const float* theta  = (const float*)d_in[3];
    const float* va     = (const float*)d_in[4];
    const void*  hp     = d_in[5];
    const void*  wp     = d_in[6];

    int N = in_sizes[0] / 3;
    if (N > MAXPTS) N = MAXPTS;

    k_main<<<GRID, THREADS>>>(PntCld, dtcCor, cam, theta, va, hp, wp,
                              N, (float*)d_out);
}

// round 16
// speedup vs baseline: 1.0692x; 1.0692x over previous
#include <cuda_runtime.h>
#include <math.h>

#define THREADS 256
#define SUB 512           // points staged per sub-tile
#define GRID 444          // 3 * 148 SMs -> one wave at occupancy 3
#define NRANGE (GRID / 2) // point ranges (each range served by 2 corner-half blocks)

// Zero-initialized scratch; kernel self-restores zeros after each run.
__device__ unsigned int g_cmax[128];  // key = ~fenc(min d2) ; 0 == "empty"
__device__ unsigned int g_ctr;
__device__ unsigned int g_ub[2];      // fenc(UB) per corner-half; 0 == "unset"

__device__ __forceinline__ float read_dim(const void* p) {
    int iv = *(const int*)p;                // little-endian: also low word of int64
    if (iv > 0 && iv < 1000000) return (float)iv;
    return *(const float*)p;
}

// Monotone total-order encoding of float -> unsigned (handles negatives).
__device__ __forceinline__ unsigned fenc(float f) {
    unsigned b = __float_as_uint(f);
    return (b & 0x80000000u) ? ~b : (b | 0x80000000u);
}
__device__ __forceinline__ float fdec(unsigned k) {
    return __uint_as_float((k & 0x80000000u) ? (k ^ 0x80000000u) : ~k);
}

__device__ __forceinline__ unsigned long long pack2(float lo, float hi) {
    unsigned long long d;
    asm("mov.b64 %0, {%1, %2};" : "=l"(d) : "f"(lo), "f"(hi));
    return d;
}
__device__ __forceinline__ void unpack2(unsigned long long d, float& lo, float& hi) {
    asm("mov.b64 {%0, %1}, %2;" : "=f"(lo), "=f"(hi) : "l"(d));
}

// One corner vs two points, replicating reference per-lane rounding:
//   t = rn(t1+s); p = rn(cx*u); d = rn(cy*v + p); d2 = rn(-2*d + t); m = min(m, d2)
__device__ __forceinline__ void corner_step(unsigned long long& m2,
                                            unsigned long long t12,
                                            unsigned long long cx2,
                                            unsigned long long cy2,
                                            unsigned long long u2,
                                            unsigned long long v2,
                                            unsigned long long s2,
                                            unsigned long long n2) {
    asm("{\n\t"
        ".reg .b64 t, p, d;\n\t"
        ".reg .f32 dlo, dhi, mlo, mhi;\n\t"
        "add.rn.f32x2 t, %1, %2;\n\t"
        "mul.rn.f32x2 p, %3, %4;\n\t"
        "fma.rn.f32x2 d, %5, %6, p;\n\t"
        "fma.rn.f32x2 d, %7, d, t;\n\t"
        "mov.b64 {dlo, dhi}, d;\n\t"
        "mov.b64 {mlo, mhi}, %0;\n\t"
        "min.f32 mlo, mlo, dlo;\n\t"
        "min.f32 mhi, mhi, dhi;\n\t"
        "mov.b64 %0, {mlo, mhi};\n\t"
        "}"
        : "+l"(m2)
        : "l"(t12), "l"(s2), "l"(cx2), "l"(u2), "l"(cy2), "l"(v2), "l"(n2));
}

__global__ void __launch_bounds__(THREADS, 3)
k_main(const float* __restrict__ P, const float* __restrict__ dtc,
       const float* __restrict__ cam, const float* __restrict__ theta,
       const float* __restrict__ va, const void* hp, const void* wp,
       int N, float* __restrict__ out) {
    __shared__ __align__(16) float su[SUB];
    __shared__ __align__(16) float sv[SUB];
    __shared__ __align__(16) float ss[SUB];
    __shared__ int   scnt;
    __shared__ float swub[8];
    __shared__ float sUB;
    __shared__ bool  isLast;
    __shared__ float red[128];

    const int tid  = threadIdx.x;
    const int warp = tid >> 5;
    const int lane = tid & 31;

    const int range = blockIdx.x >> 1;     // which point range
    const int chalf = blockIdx.x & 1;      // which 64-corner half

    // ---- Per-block fp32 camera setup (mirrors reference float32 pipeline) ----
    const float d2rf = 0.017453292519943295f;
    float rx = __fmul_rn(theta[0], d2rf);
    float ry = __fmul_rn(theta[1], d2rf);
    float rz = __fmul_rn(theta[2], d2rf);
    float cxa = cosf(rx), sxa = sinf(rx);
    float cya = cosf(ry), sya = sinf(ry);
    float cza = cosf(rz), sza = sinf(rz);
    float M01 = __fmul_rn(sya, sxa), M02 = __fmul_rn(sya, cxa);
    float M11 = cxa,                 M12 = -sxa;
    float M20 = -sya, M21 = __fmul_rn(cya, sxa), M22 = __fmul_rn(cya, cxa);
    const float R00 = __fmul_rn(cza, cya);
    const float R01 = __fsub_rn(__fmul_rn(cza, M01), __fmul_rn(sza, M11));
    const float R02 = __fsub_rn(__fmul_rn(cza, M02), __fmul_rn(sza, M12));
    const float R10 = __fmul_rn(sza, cya);
    const float R11 = __fadd_rn(__fmul_rn(sza, M01), __fmul_rn(cza, M11));
    const float R12 = __fadd_rn(__fmul_rn(sza, M02), __fmul_rn(cza, M12));
    const float R20 = M20, R21 = M21, R22 = M22;

    const float Hf = read_dim(hp), Wf = read_dim(wp);
    float vr = __fmul_rn(__fmul_rn(va[0], 0.5f), d2rf);
    const float f   = __fdiv_rn(-Hf, __fmul_rn(2.0f, tanf(vr)));
    const float kx0 = __fsub_rn(__fmul_rn(Wf, 0.5f), 0.5f);
    const float ky0 = __fsub_rn(__fmul_rn(Hf, 0.5f), 0.5f);
    const float camx = cam[0], camy = cam[1], camz = cam[2];

    // ---- This warp owns 8 corners as splatted f32x2 constants ----
    unsigned long long CX2[8], CY2[8], T12[8], M2[8];
    const int cbase = chalf * 64 + warp * 8;
#pragma unroll
    for (int k = 0; k < 8; k++) {
        int c = cbase + k;
        float ccx = dtc[2 * c], ccy = dtc[2 * c + 1];
        CX2[k] = pack2(ccx, ccx);
        CY2[k] = pack2(ccy, ccy);
        float t1 = __fadd_rn(__fmul_rn(ccx, ccx), __fmul_rn(ccy, ccy));
        T12[k] = pack2(t1, t1);
        M2[k]  = pack2(3.4e38f, 3.4e38f);
    }
    const unsigned long long N2 = pack2(-2.0f, -2.0f);

    if (tid == 0) sUB = 3.4e38f;     // first tile unfiltered
    __syncthreads();

    const int ppb   = (N + NRANGE - 1) / NRANGE;
    const int start = range * ppb;
    const int stop  = min(N, start + ppb);

    for (int base = start; base < stop; base += SUB) {
        if (tid == 0) scnt = 0;
        __syncthreads();                       // scnt visible; prior tile done

        // Effective UB: own block's bound, tightened by the global one.
        float UB = sUB;
        {
            unsigned gk = *((volatile unsigned int*)&g_ub[chalf]);
            if (gk != 0u) UB = fminf(UB, fdec(gk));
        }
        const int nval = min(SUB, stop - base);

        // Project + conservative rect-distance filter + warp compaction.
#pragma unroll
        for (int it = 0; it < SUB / THREADS; it++) {
            const int i = base + it * THREADS + tid;
            float u = 0.0f, vf = 0.0f, s = 0.0f;
            bool keep = false;
            if (i - base < nval) {
                const float* pp = P + 3 * i;
                float tx = __fadd_rn(pp[0], -camx);
                float ty = __fadd_rn(pp[1], -camy);
                float tz = __fadd_rn(pp[2], -camz);
                float x = __fmaf_rn(tz, R02, __fmaf_rn(ty, R01, __fmul_rn(tx, R00)));
                float y = __fmaf_rn(tz, R12, __fmaf_rn(ty, R11, __fmul_rn(tx, R10)));
                float z = __fmaf_rn(tz, R22, __fmaf_rn(ty, R21, __fmul_rn(tx, R20)));
                float xp = __fdiv_rn(x, z);
                float yp = __fdiv_rn(y, z);
                u  = __fmaf_rn(f, xp, kx0);
                float v = __fmaf_rn(f, yp, ky0);
                vf = __fadd_rn(Hf, -v);
                s  = __fadd_rn(__fmul_rn(u, u), __fmul_rn(vf, vf));
                // lb = squared distance from (u,vf) to the image rect that
                // contains every corner; generous margins keep this exact.
                float dx = fmaxf(fmaxf(-u, __fsub_rn(u, Wf)), 0.0f);
                float dy = fmaxf(fmaxf(-vf, __fsub_rn(vf, Hf)), 0.0f);
                float lb = __fmaf_rn(dx, dx, __fmul_rn(dy, dy));
                keep = !(__fmaf_rn(lb, 0.96f, -64.0f) > UB);   // NaN lb -> keep
            }
            unsigned mk = __ballot_sync(0xFFFFFFFFu, keep);
            if (keep) {
                int ldr  = __ffs(mk) - 1;
                int rank = __popc(mk & ((1u << lane) - 1u));
                int bpos = 0;
                if (lane == ldr) bpos = atomicAdd(&scnt, __popc(mk));
                bpos = __shfl_sync(mk, bpos, ldr);
                int pos = bpos + rank;
                su[pos] = u; sv[pos] = vf; ss[pos] = s;
            }
        }
        __syncthreads();

        const int cnt = scnt;
        const int padded = (cnt + 3) & ~3;
        if (tid < padded - cnt) {              // sentinel pad (never the min)
            su[cnt + tid] = 0.0f; sv[cnt + tid] = 0.0f; ss[cnt + tid] = 3.0e38f;
        }
        __syncthreads();

        // Inner loop: 2 points per iteration as native f32x2 operands.
        const unsigned long long* u64 = (const unsigned long long*)su;
        const unsigned long long* v64 = (const unsigned long long*)sv;
        const unsigned long long* s64 = (const unsigned long long*)ss;
        const int npair = padded >> 1;
#pragma unroll 4
        for (int j = lane; j < npair; j += 32) {
            unsigned long long u2 = u64[j];
            unsigned long long v2 = v64[j];
            unsigned long long s2 = s64[j];
#pragma unroll
            for (int k = 0; k < 8; k++)
                corner_step(M2[k], T12[k], CX2[k], CY2[k], u2, v2, s2, N2);
        }

        // Update UB: lane0's own mins upper-bound each owned corner's min.
        if (lane == 0) {
            float wmax = -3.4e38f;
#pragma unroll
            for (int k = 0; k < 8; k++) {
                float lo, hi;
                unpack2(M2[k], lo, hi);
                wmax = fmaxf(wmax, fminf(lo, hi));
            }
            swub[warp] = wmax;
        }
        __syncthreads();
        if (tid == 0) {
            float bm = swub[0];
#pragma unroll
            for (int w = 1; w < 8; w++) bm = fmaxf(bm, swub[w]);
            sUB = bm;
            atomicMin(&g_ub[chalf], fenc(bm));   // share progress across blocks
        }
        // next loop's first __syncthreads orders sUB for all readers
    }

    // Merge packed halves (even/odd points), then warp butterfly reduce.
    float m[8];
#pragma unroll
    for (int k = 0; k < 8; k++) {
        float lo, hi;
        unpack2(M2[k], lo, hi);
        m[k] = fminf(lo, hi);
    }
#pragma unroll
    for (int off = 16; off >= 1; off >>= 1) {
#pragma unroll
        for (int k = 0; k < 8; k++)
            m[k] = fminf(m[k], __shfl_xor_sync(0xFFFFFFFFu, m[k], off));
    }
    if (lane == 0) {
#pragma unroll
        for (int k = 0; k < 8; k++)
            atomicMax(&g_cmax[cbase + k], ~fenc(m[k]));   // inverted key: init 0 safe
    }

    // Last block: final deterministic sum + self-restore scratch to zero.
    __threadfence();
    __syncthreads();
    if (tid == 0) {
        unsigned old = atomicAdd(&g_ctr, 1u);
        isLast = (old == gridDim.x - 1u);
    }
    __syncthreads();
    if (isLast) {
        if (tid < 128) {
            red[tid] = fdec(~g_cmax[tid]);
            g_cmax[tid] = 0u;               // restore for next (graph) replay
        }
        if (tid == 0) { g_ctr = 0u; g_ub[0] = 0u; g_ub[1] = 0u; }
        __syncthreads();
        for (int off = 64; off > 0; off >>= 1) {
            if (tid < off) red[tid] += red[tid + off];
            __syncthreads();
        }
        if (tid == 0) out[0] = red[0];
    }
}

extern "C" void kernel_launch(void* const* d_in, const int* in_sizes, int n_in,
                              void* d_out, int out_size) {
    const float* PntCld = (const float*)d_in[0];
    const float* dtcCor = (const float*)d_in[1];
    const float* cam    = (const float*)d_in[2];
    const float* theta  = (const float*)d_in[3];
    const float* va     = (const float*)d_in[4];
    const void*  hp     = d_in[5];
    const void*  wp     = d_in[6];

    int N = in_sizes[0] / 3;

    k_main<<<GRID, THREADS>>>(PntCld, dtcCor, cam, theta, va, hp, wp,
                              N, (float*)d_out);
}